// round 1
// baseline (speedup 1.0000x reference)
#include <cuda_runtime.h>
#include <math.h>

#define EMBED  1024
#define HEADS  16
#define HD     64
#define BATCH  2
#define SEQ    2048
#define MROWS  (BATCH*SEQ)   // 4096

// ---------------- scratch (device globals; no allocation) ----------------
__device__ float g_Q[BATCH*HEADS*SEQ*HD];   // [B,H,S,D]
__device__ float g_K[BATCH*HEADS*SEQ*HD];
__device__ float g_V[BATCH*HEADS*SEQ*HD];
__device__ float g_A[MROWS*EMBED];          // merged attention output [B*S, E]

// =========================================================================
// NT SGEMM:  C[M,N] = A[M,K] * W[N,K]^T      (M=4096, N=K=1024)
// Tile 128x64x16, 256 threads, 8x4 per thread.
// mode 0/1/2: store head-split into g_Q/g_K/g_V. mode 3: A=g_A, plain store.
// =========================================================================
__global__ __launch_bounds__(256) void gemm_nt(const float* __restrict__ Ap,
                                               const float* __restrict__ W,
                                               float* __restrict__ Cext,
                                               int mode)
{
    const int K = EMBED, N = EMBED;
    __shared__ float As[16][132];   // [k][m], padded
    __shared__ float Bs[16][68];    // [k][n], padded

    const float* A = (mode == 3) ? g_A : Ap;

    int tid = threadIdx.x;
    int tx = tid & 15, ty = tid >> 4;
    int m0 = blockIdx.y * 128;
    int n0 = blockIdx.x * 64;

    float acc[8][4];
#pragma unroll
    for (int i = 0; i < 8; i++)
#pragma unroll
        for (int j = 0; j < 4; j++) acc[i][j] = 0.f;

    for (int k0 = 0; k0 < K; k0 += 16) {
        // A tile: 128x16 = 512 float4, 2 per thread
#pragma unroll
        for (int r = 0; r < 2; r++) {
            int f = tid + r * 256;
            int row = f >> 2;
            int k4 = (f & 3) * 4;
            float4 v = *(const float4*)(A + (size_t)(m0 + row) * K + k0 + k4);
            As[k4 + 0][row] = v.x; As[k4 + 1][row] = v.y;
            As[k4 + 2][row] = v.z; As[k4 + 3][row] = v.w;
        }
        // B tile: 64x16 = 256 float4, 1 per thread
        {
            int row = tid >> 2;
            int k4 = (tid & 3) * 4;
            float4 v = *(const float4*)(W + (size_t)(n0 + row) * K + k0 + k4);
            Bs[k4 + 0][row] = v.x; Bs[k4 + 1][row] = v.y;
            Bs[k4 + 2][row] = v.z; Bs[k4 + 3][row] = v.w;
        }
        __syncthreads();

#pragma unroll
        for (int kk = 0; kk < 16; kk++) {
            float4 a0 = *(const float4*)&As[kk][ty * 8];
            float4 a1 = *(const float4*)&As[kk][ty * 8 + 4];
            float4 b0 = *(const float4*)&Bs[kk][tx * 4];
            float a[8] = {a0.x, a0.y, a0.z, a0.w, a1.x, a1.y, a1.z, a1.w};
            float b[4] = {b0.x, b0.y, b0.z, b0.w};
#pragma unroll
            for (int i = 0; i < 8; i++)
#pragma unroll
                for (int j = 0; j < 4; j++)
                    acc[i][j] = fmaf(a[i], b[j], acc[i][j]);
        }
        __syncthreads();
    }

    // store
#pragma unroll
    for (int i = 0; i < 8; i++) {
        int row = m0 + ty * 8 + i;
        int col = n0 + tx * 4;
        float4 v = make_float4(acc[i][0], acc[i][1], acc[i][2], acc[i][3]);
        if (mode == 3) {
            *(float4*)(Cext + (size_t)row * N + col) = v;
        } else {
            int b = row >> 11, s = row & 2047;
            int h = col >> 6,  d = col & 63;
            float* dst = (mode == 0) ? g_Q : (mode == 1) ? g_K : g_V;
            *(float4*)(dst + (((size_t)(b * HEADS + h) * SEQ + s) * HD + d)) = v;
        }
    }
}

// =========================================================================
// Flash attention, fp32, causal. One CTA per (b*h, 64-row q tile).
// 256 threads (16x16), 4x4 per thread, online softmax with register m/l.
// Writes merged [B*S, E] layout into g_A.
// =========================================================================
#define FLASH_SMEM (4 * 64 * 68 * 4)   // Qs,Ks,Vs,Ps

__device__ __forceinline__ float redmax16(float v) {
    v = fmaxf(v, __shfl_xor_sync(0xffffffffu, v, 8));
    v = fmaxf(v, __shfl_xor_sync(0xffffffffu, v, 4));
    v = fmaxf(v, __shfl_xor_sync(0xffffffffu, v, 2));
    v = fmaxf(v, __shfl_xor_sync(0xffffffffu, v, 1));
    return v;
}
__device__ __forceinline__ float redsum16(float v) {
    v += __shfl_xor_sync(0xffffffffu, v, 8);
    v += __shfl_xor_sync(0xffffffffu, v, 4);
    v += __shfl_xor_sync(0xffffffffu, v, 2);
    v += __shfl_xor_sync(0xffffffffu, v, 1);
    return v;
}

__global__ __launch_bounds__(256) void flash_kernel()
{
    extern __shared__ float sm[];
    float* Qs = sm;               // [d][r]  64x68
    float* Ks = sm + 4352;        // [d][c]  64x68
    float* Vs = sm + 8704;        // [k][d]  64x68
    float* Ps = sm + 13056;       // [r][c]  64x68

    int tid = threadIdx.x;
    int tx = tid & 15, ty = tid >> 4;
    int bh = blockIdx.y;
    int q0 = blockIdx.x * 64;
    const float scale = 0.125f;   // 1/sqrt(64)

    size_t base = (size_t)bh * SEQ * HD;

    // Load Q tile transposed -> Qs[d][r]
#pragma unroll
    for (int r = 0; r < 4; r++) {
        int f = tid + r * 256;            // 0..1023
        int row = f >> 4;
        int d4 = (f & 15) * 4;
        float4 v = *(const float4*)(g_Q + base + (size_t)(q0 + row) * HD + d4);
        Qs[(d4 + 0) * 68 + row] = v.x; Qs[(d4 + 1) * 68 + row] = v.y;
        Qs[(d4 + 2) * 68 + row] = v.z; Qs[(d4 + 3) * 68 + row] = v.w;
    }

    float o[4][4];
#pragma unroll
    for (int i = 0; i < 4; i++)
#pragma unroll
        for (int j = 0; j < 4; j++) o[i][j] = 0.f;
    float m_r[4] = {-1e30f, -1e30f, -1e30f, -1e30f};
    float l_r[4] = {0.f, 0.f, 0.f, 0.f};

    __syncthreads();

    int ktiles = (q0 >> 6) + 1;
    for (int kt = 0; kt < ktiles; kt++) {
        int k0 = kt * 64;
        // Load K transposed -> Ks[d][c]; V natural -> Vs[k][d]
#pragma unroll
        for (int r = 0; r < 4; r++) {
            int f = tid + r * 256;
            int row = f >> 4;
            int d4 = (f & 15) * 4;
            float4 kv = *(const float4*)(g_K + base + (size_t)(k0 + row) * HD + d4);
            Ks[(d4 + 0) * 68 + row] = kv.x; Ks[(d4 + 1) * 68 + row] = kv.y;
            Ks[(d4 + 2) * 68 + row] = kv.z; Ks[(d4 + 3) * 68 + row] = kv.w;
            float4 vv = *(const float4*)(g_V + base + (size_t)(k0 + row) * HD + d4);
            *(float4*)&Vs[row * 68 + d4] = vv;
        }
        __syncthreads();

        // S = Q K^T
        float s[4][4];
#pragma unroll
        for (int i = 0; i < 4; i++)
#pragma unroll
            for (int j = 0; j < 4; j++) s[i][j] = 0.f;
#pragma unroll
        for (int d = 0; d < 64; d++) {
            float4 qa = *(const float4*)&Qs[d * 68 + ty * 4];
            float4 kb = *(const float4*)&Ks[d * 68 + tx * 4];
            float a[4] = {qa.x, qa.y, qa.z, qa.w};
            float b[4] = {kb.x, kb.y, kb.z, kb.w};
#pragma unroll
            for (int i = 0; i < 4; i++)
#pragma unroll
                for (int j = 0; j < 4; j++)
                    s[i][j] = fmaf(a[i], b[j], s[i][j]);
        }

        // scale + causal mask
        int rg = q0 + ty * 4;
        int cg = k0 + tx * 4;
#pragma unroll
        for (int i = 0; i < 4; i++)
#pragma unroll
            for (int j = 0; j < 4; j++) {
                float v = s[i][j] * scale;
                s[i][j] = (cg + j > rg + i) ? -1e30f : v;
            }

        // online softmax (m/l replicated across the 16 lanes sharing a row)
        float rs[4];
#pragma unroll
        for (int i = 0; i < 4; i++) {
            float rm = fmaxf(fmaxf(s[i][0], s[i][1]), fmaxf(s[i][2], s[i][3]));
            rm = redmax16(rm);
            float mn = fmaxf(m_r[i], rm);
            float al = __expf(m_r[i] - mn);
            float sum = 0.f;
#pragma unroll
            for (int j = 0; j < 4; j++) {
                float p = __expf(s[i][j] - mn);
                Ps[(ty * 4 + i) * 68 + tx * 4 + j] = p;
                sum += p;
            }
            rs[i] = redsum16(sum);
            l_r[i] = l_r[i] * al + rs[i];
            m_r[i] = mn;
#pragma unroll
            for (int j = 0; j < 4; j++) o[i][j] *= al;
        }
        __syncthreads();

        // O += P * V
#pragma unroll
        for (int kk = 0; kk < 64; kk++) {
            float p0 = Ps[(ty * 4 + 0) * 68 + kk];
            float p1 = Ps[(ty * 4 + 1) * 68 + kk];
            float p2 = Ps[(ty * 4 + 2) * 68 + kk];
            float p3 = Ps[(ty * 4 + 3) * 68 + kk];
            float4 vv = *(const float4*)&Vs[kk * 68 + tx * 4];
            o[0][0] = fmaf(p0, vv.x, o[0][0]); o[0][1] = fmaf(p0, vv.y, o[0][1]);
            o[0][2] = fmaf(p0, vv.z, o[0][2]); o[0][3] = fmaf(p0, vv.w, o[0][3]);
            o[1][0] = fmaf(p1, vv.x, o[1][0]); o[1][1] = fmaf(p1, vv.y, o[1][1]);
            o[1][2] = fmaf(p1, vv.z, o[1][2]); o[1][3] = fmaf(p1, vv.w, o[1][3]);
            o[2][0] = fmaf(p2, vv.x, o[2][0]); o[2][1] = fmaf(p2, vv.y, o[2][1]);
            o[2][2] = fmaf(p2, vv.z, o[2][2]); o[2][3] = fmaf(p2, vv.w, o[2][3]);
            o[3][0] = fmaf(p3, vv.x, o[3][0]); o[3][1] = fmaf(p3, vv.y, o[3][1]);
            o[3][2] = fmaf(p3, vv.z, o[3][2]); o[3][3] = fmaf(p3, vv.w, o[3][3]);
        }
        __syncthreads();
    }

    // write merged layout: [B*S, E] with col = h*64 + d
    int b = bh >> 4, h = bh & 15;
#pragma unroll
    for (int i = 0; i < 4; i++) {
        int sg = q0 + ty * 4 + i;
        float inv = 1.f / l_r[i];
        float4 v = make_float4(o[i][0] * inv, o[i][1] * inv,
                               o[i][2] * inv, o[i][3] * inv);
        *(float4*)(g_A + (size_t)(b * SEQ + sg) * EMBED + h * HD + tx * 4) = v;
    }
}

// =========================================================================
extern "C" void kernel_launch(void* const* d_in, const int* in_sizes, int n_in,
                              void* d_out, int out_size)
{
    const float* x  = (const float*)d_in[0];
    // d_in[1] = mask (bool causal) — known statically, ignored
    const float* Wq = (const float*)d_in[2];
    const float* Wk = (const float*)d_in[3];
    const float* Wv = (const float*)d_in[4];
    const float* Wo = (const float*)d_in[5];
    float* out = (float*)d_out;

    cudaFuncSetAttribute(flash_kernel,
                         cudaFuncAttributeMaxDynamicSharedMemorySize, FLASH_SMEM);

    dim3 gGemm(EMBED / 64, MROWS / 128);   // (16, 32)
    gemm_nt<<<gGemm, 256>>>(x, Wq, nullptr, 0);
    gemm_nt<<<gGemm, 256>>>(x, Wk, nullptr, 1);
    gemm_nt<<<gGemm, 256>>>(x, Wv, nullptr, 2);

    dim3 gFlash(SEQ / 64, BATCH * HEADS);  // (32, 32)
    flash_kernel<<<gFlash, 256, FLASH_SMEM>>>();

    gemm_nt<<<gGemm, 256>>>(nullptr, Wo, out, 3);
}

// round 4
// speedup vs baseline: 1.4574x; 1.4574x over previous
#include <cuda_runtime.h>
#include <cuda_bf16.h>
#include <math.h>
#include <stdint.h>

#define EMBED  1024
#define HEADS  16
#define HD     64
#define BATCH  2
#define SEQ    2048
#define MROWS  (BATCH*SEQ)   // 4096
#define KSPLIT 3072          // 3*EMBED augmented K

// ---------------- scratch (device globals; no allocation) ----------------
__device__ float g_Q[BATCH*HEADS*SEQ*HD];   // [B,H,S,D]
__device__ float g_K[BATCH*HEADS*SEQ*HD];
__device__ float g_V[BATCH*HEADS*SEQ*HD];
__device__ float g_A[MROWS*EMBED];          // merged attention output [B*S, E]
__device__ __nv_bfloat16 g_Xs[MROWS*KSPLIT];       // split activations [hi|lo|hi]
__device__ __nv_bfloat16 g_Ws[4*EMBED*KSPLIT];     // split weights     [hi|hi|lo]

// ============================ helpers ================================
__device__ __forceinline__ uint32_t smem_u32(const void* p) {
    uint32_t a;
    asm("{ .reg .u64 t; cvta.to.shared.u64 t, %1; cvt.u32.u64 %0, t; }"
        : "=r"(a) : "l"(p));
    return a;
}

__device__ __forceinline__ void cp_async16(uint32_t dst, const void* src) {
    asm volatile("cp.async.cg.shared.global [%0], [%1], 16;"
                 :: "r"(dst), "l"(src) : "memory");
}
__device__ __forceinline__ void cp_commit() {
    asm volatile("cp.async.commit_group;" ::: "memory");
}
__device__ __forceinline__ void cp_wait0() {
    asm volatile("cp.async.wait_group 0;" ::: "memory");
}

__device__ __forceinline__ void ldsm_x4(uint32_t& r0, uint32_t& r1,
                                        uint32_t& r2, uint32_t& r3, uint32_t addr) {
    asm volatile("ldmatrix.sync.aligned.m8n8.x4.shared.b16 {%0,%1,%2,%3}, [%4];"
                 : "=r"(r0), "=r"(r1), "=r"(r2), "=r"(r3) : "r"(addr));
}

__device__ __forceinline__ void mma16816(float* c, const uint32_t* a,
                                         uint32_t b0, uint32_t b1) {
    asm volatile(
        "mma.sync.aligned.m16n8k16.row.col.f32.bf16.bf16.f32 "
        "{%0,%1,%2,%3}, {%4,%5,%6,%7}, {%8,%9}, {%0,%1,%2,%3};"
        : "+f"(c[0]), "+f"(c[1]), "+f"(c[2]), "+f"(c[3])
        : "r"(a[0]), "r"(a[1]), "r"(a[2]), "r"(a[3]), "r"(b0), "r"(b1));
}

// ============================ split kernels ==============================
__global__ void split_act(const float* __restrict__ in, __nv_bfloat16* __restrict__ out) {
    int idx = blockIdx.x * 256 + threadIdx.x;      // MROWS*1024 total
    int r = idx >> 10, c = idx & 1023;
    float v = in[idx];
    __nv_bfloat16 hi = __float2bfloat16(v);
    __nv_bfloat16 lo = __float2bfloat16(v - __bfloat162float(hi));
    size_t o = (size_t)r * KSPLIT + c;
    out[o] = hi; out[o + 1024] = lo; out[o + 2048] = hi;
}

__global__ void split_wgt(const float* __restrict__ in, __nv_bfloat16* __restrict__ out) {
    int idx = blockIdx.x * 256 + threadIdx.x;      // EMBED*1024 total
    int r = idx >> 10, c = idx & 1023;
    float v = in[idx];
    __nv_bfloat16 hi = __float2bfloat16(v);
    __nv_bfloat16 lo = __float2bfloat16(v - __bfloat162float(hi));
    size_t o = (size_t)r * KSPLIT + c;
    out[o] = hi; out[o + 1024] = hi; out[o + 2048] = lo;
}

// ============================ HMMA GEMM ===============================
// C[M=4096, N=1024] = A'[M, 3072] * W'[N, 3072]^T  (bf16 in, fp32 accum)
// CTA 128x128, K-tile 64, 8 warps (2Mx4N), warp tile 64x32, cp.async dbuf.
#define KTILE   64
#define NSTEP   (KSPLIT/KTILE)          // 48
#define AST     72                      // bf16 per smem row (64 + 8 pad)
#define TILE_AB (128*AST*2)             // 18432 bytes (one operand tile)
#define BUFSZ   (2*TILE_AB)             // 36864 (A+B)
#define GEMM_SMEM (2*BUFSZ)             // 73728

__device__ __forceinline__ void load_tile(uint32_t smb, int buf,
                                          const __nv_bfloat16* __restrict__ A,
                                          const __nv_bfloat16* __restrict__ W,
                                          int m0, int n0, int kbase, int tid) {
    uint32_t base = smb + buf * BUFSZ;
#pragma unroll
    for (int i = 0; i < 4; i++) {                 // A: 1024 chunks of 16B
        int c = tid + i * 256;
        int row = c >> 3, kc = (c & 7) * 8;
        cp_async16(base + row * 144 + kc * 2,
                   A + (size_t)(m0 + row) * KSPLIT + kbase + kc);
    }
#pragma unroll
    for (int i = 0; i < 4; i++) {                 // B: 1024 chunks of 16B
        int c = tid + i * 256;
        int row = c >> 3, kc = (c & 7) * 8;
        cp_async16(base + TILE_AB + row * 144 + kc * 2,
                   W + (size_t)(n0 + row) * KSPLIT + kbase + kc);
    }
}

__global__ __launch_bounds__(256, 2) void gemm_mma(const __nv_bfloat16* __restrict__ A,
                                                   const __nv_bfloat16* __restrict__ W,
                                                   float* __restrict__ Cext, int mode)
{
    extern __shared__ char sm[];
    uint32_t smb = smem_u32(sm);
    int tid = threadIdx.x;
    int warp = tid >> 5, lane = tid & 31;
    int wm = warp & 1, wn = warp >> 1;            // 2 x 4 warp grid
    int m0 = blockIdx.y * 128;
    int n0 = blockIdx.x * 128;

    float acc[4][4][4];                            // [mf][nf][frag]
#pragma unroll
    for (int i = 0; i < 4; i++)
#pragma unroll
        for (int j = 0; j < 4; j++)
#pragma unroll
            for (int q = 0; q < 4; q++) acc[i][j][q] = 0.f;

    load_tile(smb, 0, A, W, m0, n0, 0, tid);
    cp_commit();
    cp_wait0();
    __syncthreads();

    // per-lane ldmatrix base offsets
    uint32_t aoff = (uint32_t)((wm * 64 + (lane & 15)) * 144 + (lane >> 4) * 16);
    uint32_t boff = (uint32_t)(TILE_AB + (wn * 32 + (lane & 15)) * 144 + (lane >> 4) * 16);

    for (int kt = 0; kt < NSTEP; kt++) {
        int b = kt & 1;
        if (kt + 1 < NSTEP) {
            load_tile(smb, b ^ 1, A, W, m0, n0, (kt + 1) * KTILE, tid);
            cp_commit();
        }
        uint32_t abase = smb + b * BUFSZ + aoff;
        uint32_t bbase = smb + b * BUFSZ + boff;
#pragma unroll
        for (int kk = 0; kk < 4; kk++) {           // 4 x k16
            uint32_t af[4][4];
#pragma unroll
            for (int mf = 0; mf < 4; mf++)
                ldsm_x4(af[mf][0], af[mf][1], af[mf][2], af[mf][3],
                        abase + mf * 16 * 144 + kk * 32);
#pragma unroll
            for (int nb = 0; nb < 2; nb++) {
                uint32_t b0, b1, b2, b3;
                ldsm_x4(b0, b1, b2, b3, bbase + nb * 16 * 144 + kk * 32);
#pragma unroll
                for (int mf = 0; mf < 4; mf++) {
                    mma16816(acc[mf][nb * 2 + 0], af[mf], b0, b2);
                    mma16816(acc[mf][nb * 2 + 1], af[mf], b1, b3);
                }
            }
        }
        if (kt + 1 < NSTEP) cp_wait0();
        __syncthreads();
    }

    // epilogue: c frag (m16n8): rows (lane>>2), +8; cols 2*(lane&3), +1
    int lr = lane >> 2, lc = (lane & 3) * 2;
#pragma unroll
    for (int mf = 0; mf < 4; mf++) {
#pragma unroll
        for (int nf = 0; nf < 4; nf++) {
            int col = n0 + wn * 32 + nf * 8 + lc;
#pragma unroll
            for (int half = 0; half < 2; half++) {
                int row = m0 + wm * 64 + mf * 16 + lr + half * 8;
                float2 v = make_float2(acc[mf][nf][half * 2 + 0],
                                       acc[mf][nf][half * 2 + 1]);
                if (mode == 3) {
                    *(float2*)(Cext + (size_t)row * EMBED + col) = v;
                } else {
                    int bb = row >> 11, s = row & 2047;
                    int h = col >> 6, d = col & 63;
                    float* dst = (mode == 0) ? g_Q : (mode == 1) ? g_K : g_V;
                    *(float2*)(dst + (((size_t)(bb * HEADS + h) * SEQ + s) * HD + d)) = v;
                }
            }
        }
    }
}

// =========================================================================
// Flash attention, fp32, causal (unchanged — verified).
// =========================================================================
#define FLASH_SMEM (4 * 64 * 68 * 4)

__device__ __forceinline__ float redmax16(float v) {
    v = fmaxf(v, __shfl_xor_sync(0xffffffffu, v, 8));
    v = fmaxf(v, __shfl_xor_sync(0xffffffffu, v, 4));
    v = fmaxf(v, __shfl_xor_sync(0xffffffffu, v, 2));
    v = fmaxf(v, __shfl_xor_sync(0xffffffffu, v, 1));
    return v;
}
__device__ __forceinline__ float redsum16(float v) {
    v += __shfl_xor_sync(0xffffffffu, v, 8);
    v += __shfl_xor_sync(0xffffffffu, v, 4);
    v += __shfl_xor_sync(0xffffffffu, v, 2);
    v += __shfl_xor_sync(0xffffffffu, v, 1);
    return v;
}

__global__ __launch_bounds__(256) void flash_kernel()
{
    extern __shared__ float smf[];
    float* Qs = smf;
    float* Ks = smf + 4352;
    float* Vs = smf + 8704;
    float* Ps = smf + 13056;

    int tid = threadIdx.x;
    int tx = tid & 15, ty = tid >> 4;
    int bh = blockIdx.y;
    int q0 = blockIdx.x * 64;
    const float scale = 0.125f;

    size_t base = (size_t)bh * SEQ * HD;

#pragma unroll
    for (int r = 0; r < 4; r++) {
        int f = tid + r * 256;
        int row = f >> 4;
        int d4 = (f & 15) * 4;
        float4 v = *(const float4*)(g_Q + base + (size_t)(q0 + row) * HD + d4);
        Qs[(d4 + 0) * 68 + row] = v.x; Qs[(d4 + 1) * 68 + row] = v.y;
        Qs[(d4 + 2) * 68 + row] = v.z; Qs[(d4 + 3) * 68 + row] = v.w;
    }

    float o[4][4];
#pragma unroll
    for (int i = 0; i < 4; i++)
#pragma unroll
        for (int j = 0; j < 4; j++) o[i][j] = 0.f;
    float m_r[4] = {-1e30f, -1e30f, -1e30f, -1e30f};
    float l_r[4] = {0.f, 0.f, 0.f, 0.f};

    __syncthreads();

    int ktiles = (q0 >> 6) + 1;
    for (int kt = 0; kt < ktiles; kt++) {
        int k0 = kt * 64;
#pragma unroll
        for (int r = 0; r < 4; r++) {
            int f = tid + r * 256;
            int row = f >> 4;
            int d4 = (f & 15) * 4;
            float4 kv = *(const float4*)(g_K + base + (size_t)(k0 + row) * HD + d4);
            Ks[(d4 + 0) * 68 + row] = kv.x; Ks[(d4 + 1) * 68 + row] = kv.y;
            Ks[(d4 + 2) * 68 + row] = kv.z; Ks[(d4 + 3) * 68 + row] = kv.w;
            float4 vv = *(const float4*)(g_V + base + (size_t)(k0 + row) * HD + d4);
            *(float4*)&Vs[row * 68 + d4] = vv;
        }
        __syncthreads();

        float s[4][4];
#pragma unroll
        for (int i = 0; i < 4; i++)
#pragma unroll
            for (int j = 0; j < 4; j++) s[i][j] = 0.f;
#pragma unroll
        for (int d = 0; d < 64; d++) {
            float4 qa = *(const float4*)&Qs[d * 68 + ty * 4];
            float4 kb = *(const float4*)&Ks[d * 68 + tx * 4];
            float a[4] = {qa.x, qa.y, qa.z, qa.w};
            float b[4] = {kb.x, kb.y, kb.z, kb.w};
#pragma unroll
            for (int i = 0; i < 4; i++)
#pragma unroll
                for (int j = 0; j < 4; j++)
                    s[i][j] = fmaf(a[i], b[j], s[i][j]);
        }

        int rg = q0 + ty * 4;
        int cg = k0 + tx * 4;
#pragma unroll
        for (int i = 0; i < 4; i++)
#pragma unroll
            for (int j = 0; j < 4; j++) {
                float v = s[i][j] * scale;
                s[i][j] = (cg + j > rg + i) ? -1e30f : v;
            }

        float rs[4];
#pragma unroll
        for (int i = 0; i < 4; i++) {
            float rm = fmaxf(fmaxf(s[i][0], s[i][1]), fmaxf(s[i][2], s[i][3]));
            rm = redmax16(rm);
            float mn = fmaxf(m_r[i], rm);
            float al = __expf(m_r[i] - mn);
            float sum = 0.f;
#pragma unroll
            for (int j = 0; j < 4; j++) {
                float p = __expf(s[i][j] - mn);
                Ps[(ty * 4 + i) * 68 + tx * 4 + j] = p;
                sum += p;
            }
            rs[i] = redsum16(sum);
            l_r[i] = l_r[i] * al + rs[i];
            m_r[i] = mn;
#pragma unroll
            for (int j = 0; j < 4; j++) o[i][j] *= al;
        }
        __syncthreads();

#pragma unroll
        for (int kk = 0; kk < 64; kk++) {
            float p0 = Ps[(ty * 4 + 0) * 68 + kk];
            float p1 = Ps[(ty * 4 + 1) * 68 + kk];
            float p2 = Ps[(ty * 4 + 2) * 68 + kk];
            float p3 = Ps[(ty * 4 + 3) * 68 + kk];
            float4 vv = *(const float4*)&Vs[kk * 68 + tx * 4];
            o[0][0] = fmaf(p0, vv.x, o[0][0]); o[0][1] = fmaf(p0, vv.y, o[0][1]);
            o[0][2] = fmaf(p0, vv.z, o[0][2]); o[0][3] = fmaf(p0, vv.w, o[0][3]);
            o[1][0] = fmaf(p1, vv.x, o[1][0]); o[1][1] = fmaf(p1, vv.y, o[1][1]);
            o[1][2] = fmaf(p1, vv.z, o[1][2]); o[1][3] = fmaf(p1, vv.w, o[1][3]);
            o[2][0] = fmaf(p2, vv.x, o[2][0]); o[2][1] = fmaf(p2, vv.y, o[2][1]);
            o[2][2] = fmaf(p2, vv.z, o[2][2]); o[2][3] = fmaf(p2, vv.w, o[2][3]);
            o[3][0] = fmaf(p3, vv.x, o[3][0]); o[3][1] = fmaf(p3, vv.y, o[3][1]);
            o[3][2] = fmaf(p3, vv.z, o[3][2]); o[3][3] = fmaf(p3, vv.w, o[3][3]);
        }
        __syncthreads();
    }

    int b = bh >> 4, h = bh & 15;
#pragma unroll
    for (int i = 0; i < 4; i++) {
        int sg = q0 + ty * 4 + i;
        float inv = 1.f / l_r[i];
        float4 v = make_float4(o[i][0] * inv, o[i][1] * inv,
                               o[i][2] * inv, o[i][3] * inv);
        *(float4*)(g_A + (size_t)(b * SEQ + sg) * EMBED + h * HD + tx * 4) = v;
    }
}

// =========================================================================
extern "C" void kernel_launch(void* const* d_in, const int* in_sizes, int n_in,
                              void* d_out, int out_size)
{
    const float* x  = (const float*)d_in[0];
    const float* Wq = (const float*)d_in[2];
    const float* Wk = (const float*)d_in[3];
    const float* Wv = (const float*)d_in[4];
    const float* Wo = (const float*)d_in[5];
    float* out = (float*)d_out;

    __nv_bfloat16 *dXs, *dWs;
    float *dA;
    cudaGetSymbolAddress((void**)&dXs, g_Xs);
    cudaGetSymbolAddress((void**)&dWs, g_Ws);
    cudaGetSymbolAddress((void**)&dA, g_A);

    cudaFuncSetAttribute(flash_kernel,
                         cudaFuncAttributeMaxDynamicSharedMemorySize, FLASH_SMEM);
    cudaFuncSetAttribute(gemm_mma,
                         cudaFuncAttributeMaxDynamicSharedMemorySize, GEMM_SMEM);

    const size_t WSZ = (size_t)EMBED * KSPLIT;

    // split activations + weights
    split_act<<<MROWS * 1024 / 256, 256>>>(x, dXs);
    split_wgt<<<EMBED * 1024 / 256, 256>>>(Wq, dWs + 0 * WSZ);
    split_wgt<<<EMBED * 1024 / 256, 256>>>(Wk, dWs + 1 * WSZ);
    split_wgt<<<EMBED * 1024 / 256, 256>>>(Wv, dWs + 2 * WSZ);
    split_wgt<<<EMBED * 1024 / 256, 256>>>(Wo, dWs + 3 * WSZ);

    // Q/K/V projections on tensor cores (HMMA)
    dim3 gGemm(EMBED / 128, MROWS / 128);   // (8, 32)
    gemm_mma<<<gGemm, 256, GEMM_SMEM>>>(dXs, dWs + 0 * WSZ, nullptr, 0);
    gemm_mma<<<gGemm, 256, GEMM_SMEM>>>(dXs, dWs + 1 * WSZ, nullptr, 1);
    gemm_mma<<<gGemm, 256, GEMM_SMEM>>>(dXs, dWs + 2 * WSZ, nullptr, 2);

    // attention
    dim3 gFlash(SEQ / 64, BATCH * HEADS);  // (32, 32)
    flash_kernel<<<gFlash, 256, FLASH_SMEM>>>();

    // split attention output, O projection
    split_act<<<MROWS * 1024 / 256, 256>>>(dA, dXs);
    gemm_mma<<<gGemm, 256, GEMM_SMEM>>>(dXs, dWs + 3 * WSZ, out, 3);
}

// round 5
// speedup vs baseline: 2.4116x; 1.6548x over previous
#include <cuda_runtime.h>
#include <cuda_bf16.h>
#include <math.h>
#include <stdint.h>

#define EMBED  1024
#define HEADS  16
#define HD     64
#define BATCH  2
#define SEQ    2048
#define MROWS  (BATCH*SEQ)   // 4096
#define KSPLIT 3072          // 3*EMBED augmented K
#define SC2F   0.1803368801111601f   // (1/sqrt(64)) * log2(e)

// ---------------- scratch (device globals; no allocation) ----------------
__device__ __nv_bfloat16 g_Xs[MROWS*KSPLIT];       // split activations [hi|lo|hi]
__device__ __nv_bfloat16 g_Ws[4*EMBED*KSPLIT];     // split weights     [hi|hi|lo]
__device__ __nv_bfloat16 g_Qh[BATCH*HEADS*SEQ*HD]; // bf16 hi/lo, [bh][s][d]
__device__ __nv_bfloat16 g_Ql[BATCH*HEADS*SEQ*HD];
__device__ __nv_bfloat16 g_Kh[BATCH*HEADS*SEQ*HD];
__device__ __nv_bfloat16 g_Kl[BATCH*HEADS*SEQ*HD];
__device__ __nv_bfloat16 g_Vh[BATCH*HEADS*SEQ*HD];
__device__ __nv_bfloat16 g_Vl[BATCH*HEADS*SEQ*HD];

// ============================ helpers ================================
__device__ __forceinline__ uint32_t smem_u32(const void* p) {
    uint32_t a;
    asm("{ .reg .u64 t; cvta.to.shared.u64 t, %1; cvt.u32.u64 %0, t; }"
        : "=r"(a) : "l"(p));
    return a;
}
__device__ __forceinline__ void cp_async16(uint32_t dst, const void* src) {
    asm volatile("cp.async.cg.shared.global [%0], [%1], 16;"
                 :: "r"(dst), "l"(src) : "memory");
}
__device__ __forceinline__ void cp_commit() {
    asm volatile("cp.async.commit_group;" ::: "memory");
}
__device__ __forceinline__ void cp_wait0() {
    asm volatile("cp.async.wait_group 0;" ::: "memory");
}
__device__ __forceinline__ void cp_wait1() {
    asm volatile("cp.async.wait_group 1;" ::: "memory");
}
__device__ __forceinline__ void ldsm_x4(uint32_t& r0, uint32_t& r1,
                                        uint32_t& r2, uint32_t& r3, uint32_t addr) {
    asm volatile("ldmatrix.sync.aligned.m8n8.x4.shared.b16 {%0,%1,%2,%3}, [%4];"
                 : "=r"(r0), "=r"(r1), "=r"(r2), "=r"(r3) : "r"(addr));
}
__device__ __forceinline__ void ldsm_x4t(uint32_t& r0, uint32_t& r1,
                                         uint32_t& r2, uint32_t& r3, uint32_t addr) {
    asm volatile("ldmatrix.sync.aligned.m8n8.x4.trans.shared.b16 {%0,%1,%2,%3}, [%4];"
                 : "=r"(r0), "=r"(r1), "=r"(r2), "=r"(r3) : "r"(addr));
}
__device__ __forceinline__ void mma16816(float* c, const uint32_t* a,
                                         uint32_t b0, uint32_t b1) {
    asm volatile(
        "mma.sync.aligned.m16n8k16.row.col.f32.bf16.bf16.f32 "
        "{%0,%1,%2,%3}, {%4,%5,%6,%7}, {%8,%9}, {%0,%1,%2,%3};"
        : "+f"(c[0]), "+f"(c[1]), "+f"(c[2]), "+f"(c[3])
        : "r"(a[0]), "r"(a[1]), "r"(a[2]), "r"(a[3]), "r"(b0), "r"(b1));
}
// pack: lo half = a, hi half = b
__device__ __forceinline__ uint32_t bf16x2(float a, float b) {
    uint32_t r;
    asm("cvt.rn.bf16x2.f32 %0, %1, %2;" : "=r"(r) : "f"(b), "f"(a));
    return r;
}
// fma-pipe exp2 (Taylor-4, rel err ~4e-5), input clamped to [-80, 0]
__device__ __forceinline__ float exp2_poly(float d) {
    d = fmaxf(d, -80.f);
    float t = d + 12582912.f;                   // round-to-nearest int
    int ib = __float_as_int(t);                 // (ib<<23) == n<<23 (magic wraps out)
    float f = d - (t - 12582912.f);             // f in [-0.5, 0.5]
    float p = 0.009618130f;
    p = fmaf(p, f, 0.055504110f);
    p = fmaf(p, f, 0.240226507f);
    p = fmaf(p, f, 0.693147181f);
    p = fmaf(p, f, 1.0f);
    return __int_as_float(__float_as_int(p) + (ib << 23));
}

// ============================ split kernels ==============================
__global__ void split_act(const float* __restrict__ in, __nv_bfloat16* __restrict__ out) {
    int idx = blockIdx.x * 256 + threadIdx.x;
    int r = idx >> 10, c = idx & 1023;
    float v = in[idx];
    __nv_bfloat16 hi = __float2bfloat16(v);
    __nv_bfloat16 lo = __float2bfloat16(v - __bfloat162float(hi));
    size_t o = (size_t)r * KSPLIT + c;
    out[o] = hi; out[o + 1024] = lo; out[o + 2048] = hi;
}
__global__ void split_wgt(const float* __restrict__ in, __nv_bfloat16* __restrict__ out) {
    int idx = blockIdx.x * 256 + threadIdx.x;
    int r = idx >> 10, c = idx & 1023;
    float v = in[idx];
    __nv_bfloat16 hi = __float2bfloat16(v);
    __nv_bfloat16 lo = __float2bfloat16(v - __bfloat162float(hi));
    size_t o = (size_t)r * KSPLIT + c;
    out[o] = hi; out[o + 1024] = hi; out[o + 2048] = lo;
}

// ============================ HMMA GEMM ===============================
// C[4096,1024] = A'[4096,3072] * W'[1024,3072]^T  (bf16 in, fp32 accum)
#define KTILE   64
#define NSTEP   (KSPLIT/KTILE)          // 48
#define TILE_AB (128*144)               // bytes per operand tile (row stride 144B)
#define BUFSZ   (2*TILE_AB)
#define GEMM_SMEM (2*BUFSZ)             // 73728

__device__ __forceinline__ void load_tile(uint32_t smb, int buf,
                                          const __nv_bfloat16* __restrict__ A,
                                          const __nv_bfloat16* __restrict__ W,
                                          int m0, int n0, int kbase, int tid) {
    uint32_t base = smb + buf * BUFSZ;
#pragma unroll
    for (int i = 0; i < 4; i++) {
        int c = tid + i * 256;
        int row = c >> 3, kc = (c & 7) * 8;
        cp_async16(base + row * 144 + kc * 2,
                   A + (size_t)(m0 + row) * KSPLIT + kbase + kc);
    }
#pragma unroll
    for (int i = 0; i < 4; i++) {
        int c = tid + i * 256;
        int row = c >> 3, kc = (c & 7) * 8;
        cp_async16(base + TILE_AB + row * 144 + kc * 2,
                   W + (size_t)(n0 + row) * KSPLIT + kbase + kc);
    }
}

__global__ __launch_bounds__(256, 2) void gemm_mma(const __nv_bfloat16* __restrict__ A,
                                                   const __nv_bfloat16* __restrict__ W,
                                                   float* __restrict__ Cext, int mode)
{
    extern __shared__ char sm[];
    uint32_t smb = smem_u32(sm);
    int tid = threadIdx.x;
    int warp = tid >> 5, lane = tid & 31;
    int wm = warp & 1, wn = warp >> 1;
    int m0 = blockIdx.y * 128;
    int n0 = blockIdx.x * 128;

    float acc[4][4][4];
#pragma unroll
    for (int i = 0; i < 4; i++)
#pragma unroll
        for (int j = 0; j < 4; j++)
#pragma unroll
            for (int q = 0; q < 4; q++) acc[i][j][q] = 0.f;

    load_tile(smb, 0, A, W, m0, n0, 0, tid);
    cp_commit();
    cp_wait0();
    __syncthreads();

    uint32_t aoff = (uint32_t)((wm * 64 + (lane & 15)) * 144 + (lane >> 4) * 16);
    uint32_t boff = (uint32_t)(TILE_AB + (wn * 32 + (lane & 15)) * 144 + (lane >> 4) * 16);

    for (int kt = 0; kt < NSTEP; kt++) {
        int b = kt & 1;
        if (kt + 1 < NSTEP) {
            load_tile(smb, b ^ 1, A, W, m0, n0, (kt + 1) * KTILE, tid);
            cp_commit();
        }
        uint32_t abase = smb + b * BUFSZ + aoff;
        uint32_t bbase = smb + b * BUFSZ + boff;
#pragma unroll
        for (int kk = 0; kk < 4; kk++) {
            uint32_t af[4][4];
#pragma unroll
            for (int mf = 0; mf < 4; mf++)
                ldsm_x4(af[mf][0], af[mf][1], af[mf][2], af[mf][3],
                        abase + mf * 16 * 144 + kk * 32);
#pragma unroll
            for (int nb = 0; nb < 2; nb++) {
                uint32_t b0, b1, b2, b3;
                ldsm_x4(b0, b1, b2, b3, bbase + nb * 16 * 144 + kk * 32);
#pragma unroll
                for (int mf = 0; mf < 4; mf++) {
                    mma16816(acc[mf][nb * 2 + 0], af[mf], b0, b2);
                    mma16816(acc[mf][nb * 2 + 1], af[mf], b1, b3);
                }
            }
        }
        if (kt + 1 < NSTEP) cp_wait0();
        __syncthreads();
    }

    int lr = lane >> 2, lc = (lane & 3) * 2;
#pragma unroll
    for (int mf = 0; mf < 4; mf++) {
#pragma unroll
        for (int nf = 0; nf < 4; nf++) {
            int col = n0 + wn * 32 + nf * 8 + lc;
#pragma unroll
            for (int half = 0; half < 2; half++) {
                int row = m0 + wm * 64 + mf * 16 + lr + half * 8;
                float vx = acc[mf][nf][half * 2 + 0];
                float vy = acc[mf][nf][half * 2 + 1];
                if (mode == 3) {
                    *(float2*)(Cext + (size_t)row * EMBED + col) = make_float2(vx, vy);
                } else {
                    if (mode == 0) { vx *= SC2F; vy *= SC2F; }
                    uint32_t hp = bf16x2(vx, vy);
                    float h0 = __int_as_float(hp << 16);
                    float h1 = __int_as_float(hp & 0xFFFF0000u);
                    uint32_t lp = bf16x2(vx - h0, vy - h1);
                    int bb = row >> 11, s = row & 2047;
                    int h = col >> 6, d = col & 63;
                    size_t idx = (((size_t)(bb * HEADS + h) * SEQ + s) * HD + d);
                    __nv_bfloat16 *dh, *dl;
                    if (mode == 0)      { dh = g_Qh; dl = g_Ql; }
                    else if (mode == 1) { dh = g_Kh; dl = g_Kl; }
                    else                { dh = g_Vh; dl = g_Vl; }
                    *(uint32_t*)(dh + idx) = hp;
                    *(uint32_t*)(dl + idx) = lp;
                }
            }
        }
    }
}

// =========================================================================
// Flash attention v2: HMMA split-bf16, log2-domain softmax, hybrid exp.
// CTA = 256 thr (8 warps), qtile 128 rows, ktile 64 keys.
// smem: Q2[128][136] | 2 x ( K2[64][136] , V2[128][72] )   (bf16)
// =========================================================================
#define QSTR  272               // Q2/K2 row stride bytes (136 bf16)
#define VSTR  144               // V2 row stride bytes (72 bf16)
#define Q2SZ  (128*QSTR)        // 34816
#define K2SZ  (64*QSTR)         // 17408
#define V2SZ  (128*VSTR)        // 18432
#define KVSZ  (K2SZ+V2SZ)
#define FLASH_SMEM (Q2SZ + 2*KVSZ)   // 106496

__device__ __forceinline__ void flash_load_kv(uint32_t smb, int buf, int k0,
                                              const __nv_bfloat16* Kh, const __nv_bfloat16* Kl,
                                              const __nv_bfloat16* Vh, const __nv_bfloat16* Vl,
                                              int tid) {
    uint32_t kb = smb + Q2SZ + buf * KVSZ;
    uint32_t vb = kb + K2SZ;
#pragma unroll
    for (int i = 0; i < 4; i++) {               // K: 1024 x 16B
        int id = tid + i * 256;
        int row = id >> 4, half = (id >> 3) & 1, c8 = id & 7;
        cp_async16(kb + row * QSTR + half * 128 + c8 * 16,
                   (half ? Kl : Kh) + (size_t)(k0 + row) * HD + c8 * 8);
    }
#pragma unroll
    for (int i = 0; i < 4; i++) {               // V: 1024 x 16B
        int id = tid + i * 256;
        int row = id >> 3, c8 = id & 7;         // row 0..127: [vhi;vlo]
        cp_async16(vb + row * VSTR + c8 * 16,
                   (row < 64 ? Vh : Vl) + (size_t)(k0 + (row & 63)) * HD + c8 * 8);
    }
}

__global__ __launch_bounds__(256, 1) void flash2()
{
    extern __shared__ char sm[];
    uint32_t smb = smem_u32(sm);
    int tid = threadIdx.x;
    int warp = tid >> 5, lane = tid & 31;
    int bh = blockIdx.y;
    int qt = (int)gridDim.x - 1 - blockIdx.x;   // heavy tiles first
    int q0 = qt * 128;

    size_t base = (size_t)bh * SEQ * HD;
    const __nv_bfloat16 *Qh = g_Qh + base, *Ql = g_Ql + base;
    const __nv_bfloat16 *Kh = g_Kh + base, *Kl = g_Kl + base;
    const __nv_bfloat16 *Vh = g_Vh + base, *Vl = g_Vl + base;

    // Q2 load: 2048 x 16B chunks; row = [qhi(64) | qlo(64)]
#pragma unroll
    for (int i = 0; i < 8; i++) {
        int id = tid + i * 256;
        int row = id >> 4, half = (id >> 3) & 1, c8 = id & 7;
        cp_async16(smb + row * QSTR + half * 128 + c8 * 16,
                   (half ? Ql : Qh) + (size_t)(q0 + row) * HD + c8 * 8);
    }
    flash_load_kv(smb, 0, 0, Kh, Kl, Vh, Vl, tid);
    cp_commit();

    float O[8][4];
#pragma unroll
    for (int f = 0; f < 8; f++)
#pragma unroll
        for (int q = 0; q < 4; q++) O[f][q] = 0.f;
    float m0v = -1e30f, m1v = -1e30f, l0 = 0.f, l1 = 0.f;

    uint32_t aoff = (uint32_t)((warp * 16 + (lane & 15)) * QSTR + (lane >> 4) * 16);
    uint32_t koff = (uint32_t)((lane & 15) * QSTR + (lane >> 4) * 16);
    uint32_t voff = (uint32_t)((lane & 15) * VSTR + (lane >> 4) * 16);

    int nkt = 2 * (qt + 1);
    int rg0 = q0 + warp * 16 + (lane >> 2);     // this thread's first row
    int cg0 = 2 * (lane & 3);                   // col offset within 8-col frag

    for (int kt = 0; kt < nkt; kt++) {
        int buf = kt & 1;
        int k0 = kt * 64;
        if (kt + 1 < nkt) {
            flash_load_kv(smb, buf ^ 1, (kt + 1) * 64, Kh, Kl, Vh, Vl, tid);
            cp_commit();
            cp_wait1();
        } else {
            cp_wait0();
        }
        __syncthreads();

        // ---- S = Q' K'^T  (12 logical k16 chunks) ----
        float S[8][4];
#pragma unroll
        for (int f = 0; f < 8; f++)
#pragma unroll
            for (int q = 0; q < 4; q++) S[f][q] = 0.f;
        uint32_t kbuf = smb + Q2SZ + buf * KVSZ;
#pragma unroll
        for (int c = 0; c < 12; c++) {
            int ac = (c < 8) ? c : c - 8;                 // qhi|qlo|qhi
            int bc = (c < 8) ? (c & 3) : 4 + (c & 3);     // khi|khi|klo
            uint32_t a[4];
            ldsm_x4(a[0], a[1], a[2], a[3], smb + aoff + ac * 32);
#pragma unroll
            for (int g = 0; g < 4; g++) {
                uint32_t b0, b1, b2, b3;
                ldsm_x4(b0, b1, b2, b3, kbuf + koff + g * 16 * QSTR + bc * 32);
                mma16816(S[2 * g + 0], a, b0, b2);
                mma16816(S[2 * g + 1], a, b1, b3);
            }
        }

        // ---- causal mask (only last two tiles can clip) ----
        if (kt >= nkt - 2) {
#pragma unroll
            for (int f = 0; f < 8; f++) {
                int key = k0 + 8 * f + cg0;
#pragma unroll
                for (int q = 0; q < 4; q++) {
                    int kcol = key + (q & 1);
                    int row = rg0 + (q >> 1) * 8;
                    if (kcol > row) S[f][q] = -1e30f;
                }
            }
        }

        // ---- online softmax (log2 domain) ----
        float mx0 = -1e30f, mx1 = -1e30f;
#pragma unroll
        for (int f = 0; f < 8; f++) {
            mx0 = fmaxf(mx0, fmaxf(S[f][0], S[f][1]));
            mx1 = fmaxf(mx1, fmaxf(S[f][2], S[f][3]));
        }
        mx0 = fmaxf(mx0, __shfl_xor_sync(0xffffffffu, mx0, 1));
        mx0 = fmaxf(mx0, __shfl_xor_sync(0xffffffffu, mx0, 2));
        mx1 = fmaxf(mx1, __shfl_xor_sync(0xffffffffu, mx1, 1));
        mx1 = fmaxf(mx1, __shfl_xor_sync(0xffffffffu, mx1, 2));
        float mn0 = fmaxf(m0v, mx0), mn1 = fmaxf(m1v, mx1);
        float al0 = exp2f(m0v - mn0), al1 = exp2f(m1v - mn1);
        m0v = mn0; m1v = mn1;

        float rs0 = 0.f, rs1 = 0.f;
#pragma unroll
        for (int f = 0; f < 8; f++) {
            if (f < 3) {                       // fma-pipe poly path
                S[f][0] = exp2_poly(S[f][0] - mn0);
                S[f][1] = exp2_poly(S[f][1] - mn0);
                S[f][2] = exp2_poly(S[f][2] - mn1);
                S[f][3] = exp2_poly(S[f][3] - mn1);
            } else {                           // MUFU path
                S[f][0] = exp2f(S[f][0] - mn0);
                S[f][1] = exp2f(S[f][1] - mn0);
                S[f][2] = exp2f(S[f][2] - mn1);
                S[f][3] = exp2f(S[f][3] - mn1);
            }
            rs0 += S[f][0] + S[f][1];
            rs1 += S[f][2] + S[f][3];
        }
        rs0 += __shfl_xor_sync(0xffffffffu, rs0, 1);
        rs0 += __shfl_xor_sync(0xffffffffu, rs0, 2);
        rs1 += __shfl_xor_sync(0xffffffffu, rs1, 1);
        rs1 += __shfl_xor_sync(0xffffffffu, rs1, 2);
        l0 = l0 * al0 + rs0;
        l1 = l1 * al1 + rs1;

#pragma unroll
        for (int f = 0; f < 8; f++) {
            O[f][0] *= al0; O[f][1] *= al0;
            O[f][2] *= al1; O[f][3] *= al1;
        }

        // ---- split P into bf16 hi/lo packs (A-operand layout) ----
        uint32_t PH[8][2], PL[8][2];
#pragma unroll
        for (int f = 0; f < 8; f++) {
            uint32_t h01 = bf16x2(S[f][0], S[f][1]);
            uint32_t h23 = bf16x2(S[f][2], S[f][3]);
            PH[f][0] = h01; PH[f][1] = h23;
            float e0 = S[f][0] - __int_as_float(h01 << 16);
            float e1 = S[f][1] - __int_as_float(h01 & 0xFFFF0000u);
            float e2 = S[f][2] - __int_as_float(h23 << 16);
            float e3 = S[f][3] - __int_as_float(h23 & 0xFFFF0000u);
            PL[f][0] = bf16x2(e0, e1);
            PL[f][1] = bf16x2(e2, e3);
        }

        // ---- O += P' V''  (12 logical k16 chunks) ----
        uint32_t vbuf = kbuf + K2SZ;
#pragma unroll
        for (int c = 0; c < 12; c++) {
            int j = (c < 4) ? c : (c < 8 ? c - 4 : c - 8);
            int vrow = (c < 4) ? 16 * c : (c < 8 ? 16 * (c - 4) : 64 + 16 * (c - 8));
            uint32_t a[4];
            if (c < 4 || c >= 8) {
                a[0] = PH[2 * j][0]; a[1] = PH[2 * j][1];
                a[2] = PH[2 * j + 1][0]; a[3] = PH[2 * j + 1][1];
            } else {
                a[0] = PL[2 * j][0]; a[1] = PL[2 * j][1];
                a[2] = PL[2 * j + 1][0]; a[3] = PL[2 * j + 1][1];
            }
#pragma unroll
            for (int p = 0; p < 4; p++) {
                uint32_t b0, b1, b2, b3;
                ldsm_x4t(b0, b1, b2, b3, vbuf + voff + vrow * VSTR + p * 32);
                mma16816(O[2 * p + 0], a, b0, b1);
                mma16816(O[2 * p + 1], a, b2, b3);
            }
        }
        __syncthreads();
    }

    // ---- epilogue: write split-bf16 into g_Xs ([row][hi|lo|hi], stride 3072)
    float inv0 = 1.f / l0, inv1 = 1.f / l1;
    int b = bh >> 4, h = bh & 15;
#pragma unroll
    for (int f = 0; f < 8; f++) {
        int col = h * HD + 8 * f + cg0;
#pragma unroll
        for (int half = 0; half < 2; half++) {
            int row = b * SEQ + q0 + warp * 16 + (lane >> 2) + half * 8;
            float vx = O[f][half * 2 + 0] * (half ? inv1 : inv0);
            float vy = O[f][half * 2 + 1] * (half ? inv1 : inv0);
            uint32_t hp = bf16x2(vx, vy);
            float h0 = __int_as_float(hp << 16);
            float h1 = __int_as_float(hp & 0xFFFF0000u);
            uint32_t lp = bf16x2(vx - h0, vy - h1);
            __nv_bfloat16* dst = g_Xs + (size_t)row * KSPLIT + col;
            *(uint32_t*)(dst)        = hp;
            *(uint32_t*)(dst + 1024) = lp;
            *(uint32_t*)(dst + 2048) = hp;
        }
    }
}

// =========================================================================
extern "C" void kernel_launch(void* const* d_in, const int* in_sizes, int n_in,
                              void* d_out, int out_size)
{
    const float* x  = (const float*)d_in[0];
    const float* Wq = (const float*)d_in[2];
    const float* Wk = (const float*)d_in[3];
    const float* Wv = (const float*)d_in[4];
    const float* Wo = (const float*)d_in[5];
    float* out = (float*)d_out;

    __nv_bfloat16 *dXs, *dWs;
    cudaGetSymbolAddress((void**)&dXs, g_Xs);
    cudaGetSymbolAddress((void**)&dWs, g_Ws);

    cudaFuncSetAttribute(gemm_mma,
                         cudaFuncAttributeMaxDynamicSharedMemorySize, GEMM_SMEM);
    cudaFuncSetAttribute(flash2,
                         cudaFuncAttributeMaxDynamicSharedMemorySize, FLASH_SMEM);

    const size_t WSZ = (size_t)EMBED * KSPLIT;

    // split inputs
    split_act<<<MROWS * 1024 / 256, 256>>>(x, dXs);
    split_wgt<<<EMBED * 1024 / 256, 256>>>(Wq, dWs + 0 * WSZ);
    split_wgt<<<EMBED * 1024 / 256, 256>>>(Wk, dWs + 1 * WSZ);
    split_wgt<<<EMBED * 1024 / 256, 256>>>(Wv, dWs + 2 * WSZ);
    split_wgt<<<EMBED * 1024 / 256, 256>>>(Wo, dWs + 3 * WSZ);

    // Q/K/V projections (HMMA), epilogues emit pre-split bf16
    dim3 gGemm(EMBED / 128, MROWS / 128);
    gemm_mma<<<gGemm, 256, GEMM_SMEM>>>(dXs, dWs + 0 * WSZ, nullptr, 0);
    gemm_mma<<<gGemm, 256, GEMM_SMEM>>>(dXs, dWs + 1 * WSZ, nullptr, 1);
    gemm_mma<<<gGemm, 256, GEMM_SMEM>>>(dXs, dWs + 2 * WSZ, nullptr, 2);

    // attention (writes split A directly into g_Xs)
    dim3 gFlash(SEQ / 128, BATCH * HEADS);   // (16, 32)
    flash2<<<gFlash, 256, FLASH_SMEM>>>();

    // O projection
    gemm_mma<<<gGemm, 256, GEMM_SMEM>>>(dXs, dWs + 3 * WSZ, out, 3);
}